// round 13
// baseline (speedup 1.0000x reference)
#include <cuda_runtime.h>
#include <math.h>

#define HH 512
#define WW 512
#define NACC 72          // 45 M upper-tri + 27 moment-Atb (unscaled by SH consts)
#define NXB 2
#define NSTR 37
#define NPART (NXB * NSTR)   // 74 blocks per batch image
#define BMAX 8

__device__ float g_part[BMAX * NPART * NACC];

typedef unsigned long long u64;

__device__ __forceinline__ u64 pk2(float lo, float hi) {
    u64 r; asm("mov.b64 %0,{%1,%2};" : "=l"(r) : "f"(lo), "f"(hi)); return r;
}
__device__ __forceinline__ void upk2(u64 a, float& lo, float& hi) {
    asm("mov.b64 {%0,%1},%2;" : "=f"(lo), "=f"(hi) : "l"(a));
}
__device__ __forceinline__ u64 fma2(u64 a, u64 b, u64 c) {
    u64 d; asm("fma.rn.f32x2 %0,%1,%2,%3;" : "=l"(d) : "l"(a), "l"(b), "l"(c)); return d;
}
__device__ __forceinline__ u64 mul2(u64 a, u64 b) {
    u64 d; asm("mul.rn.f32x2 %0,%1,%2;" : "=l"(d) : "l"(a), "l"(b)); return d;
}
__device__ __forceinline__ u64 add2(u64 a, u64 b) {
    u64 d; asm("add.rn.f32x2 %0,%1,%2;" : "=l"(d) : "l"(a), "l"(b)); return d;
}
__device__ __forceinline__ u64 neg2(u64 a) { return a ^ 0x8000000080000000ULL; }
__device__ __forceinline__ u64 sub2(u64 a, u64 b) { return fma2(b, 0xBF800000BF800000ULL, a); }
__device__ __forceinline__ u64 fms2(u64 a, u64 b, u64 c) { return fma2(a, b, neg2(c)); }
__device__ __forceinline__ u64 bcast2(float v) { return pk2(v, v); }

__device__ __forceinline__ int triidx(int i, int j) {   // upper-tri, i<=j
    return 9 * i - (i * (i - 1)) / 2 + (j - i);
}

__global__ __launch_bounds__(128) void accum_k(const float* __restrict__ img,
                                               const float* __restrict__ dep,
                                               const float* __restrict__ alb) {
    const int tid = threadIdx.x;
    const int xb = blockIdx.x;   // 0..1
    const int st = blockIdx.y;   // 0..36
    const int b  = blockIdx.z;

    const int x_lo = 1 + xb * 256 + tid;    // <= 384, always valid
    int x_hi = x_lo + 128;
    const bool v_hi = (x_hi <= 510);
    if (!v_hi) x_hi = 510;                  // clamp; contribution zeroed below

    const int y0 = 1 + (510 * st) / NSTR;
    const int y1 = 1 + (510 * (st + 1)) / NSTR;

    const float* __restrict__ D  = dep + (size_t)b * HH * WW;
    const float* __restrict__ I0 = img + (size_t)b * 3 * HH * WW;
    const float* __restrict__ I1 = I0 + HH * WW;
    const float* __restrict__ I2 = I1 + HH * WW;
    const float* __restrict__ A2 = alb + (size_t)b * 3 * HH * WW + 2 * HH * WW;

    const float INVF = (float)(1.0 / 608.365);
    const u64 HALF2  = 0x3F0000003F000000ULL;
    const u64 THREE2 = 0x4040000040400000ULL;

    const u64 u2  = pk2((x_lo     - 256.0f) * INVF, (x_hi     - 256.0f) * INVF);
    const u64 uE2 = pk2((x_lo + 1 - 256.0f) * INVF, (x_hi + 1 - 256.0f) * INVF);
    const u64 uW2 = pk2((x_lo - 1 - 256.0f) * INVF, (x_hi - 1 - 256.0f) * INVF);

    u64 s2[NACC];
#pragma unroll
    for (int k = 0; k < NACC; k++) s2[k] = 0ULL;

    // rolling center-column depth (transformed)
    u64 dN2 = fma2(pk2(D[(y0 - 1) * WW + x_lo], D[(y0 - 1) * WW + x_hi]), HALF2, HALF2);
    u64 dC2 = fma2(pk2(D[y0 * WW + x_lo],       D[y0 * WW + x_hi]),       HALF2, HALF2);

    // 2-deep software pipeline: slot a = row y, slot b = row y+1.
    // Max consumed row is 510 (south neighbor 511 valid); prefetch clamps to
    // 510 -> reads at most row 511 (in-bounds); the clamped duplicate slot is
    // only created PAST the last consumed row and is never read.
    int ra = y0 * WW;
    u64 aS = pk2(D[ra + WW + x_lo], D[ra + WW + x_hi]);
    u64 aE = pk2(D[ra + x_lo + 1],  D[ra + x_hi + 1]);
    u64 aW = pk2(D[ra + x_lo - 1],  D[ra + x_hi - 1]);
    float a0l = I0[ra + x_lo], a0h = I0[ra + x_hi];
    float a1l = I1[ra + x_lo], a1h = I1[ra + x_hi];
    float a2l = I2[ra + x_lo], a2h = I2[ra + x_hi];
    float aal = A2[ra + x_lo], aah = A2[ra + x_hi];

    int rb = (y0 + 1 <= 510 ? y0 + 1 : 510) * WW;
    u64 bS = pk2(D[rb + WW + x_lo], D[rb + WW + x_hi]);
    u64 bE = pk2(D[rb + x_lo + 1],  D[rb + x_hi + 1]);
    u64 bW = pk2(D[rb + x_lo - 1],  D[rb + x_hi - 1]);
    float b0l = I0[rb + x_lo], b0h = I0[rb + x_hi];
    float b1l = I1[rb + x_lo], b1h = I1[rb + x_hi];
    float b2l = I2[rb + x_lo], b2h = I2[rb + x_hi];
    float bal = A2[rb + x_lo], bah = A2[rb + x_hi];

#pragma unroll 2
    for (int y = y0; y < y1; y++) {
        // consume slot a (row y)
        const u64 dS2 = fma2(aS, HALF2, HALF2);
        const u64 dE2 = fma2(aE, HALF2, HALF2);
        const u64 dW2 = fma2(aW, HALF2, HALF2);
        const float g0l = a0l, g0h = a0h;
        const float g1l = a1l, g1h = a1h;
        const float g2l = a2l, g2h = a2h;
        const float all_ = aal, alh = aah;

        // shift b -> a  (renamed away by the unroll-2)
        aS = bS; aE = bE; aW = bW;
        a0l = b0l; a0h = b0h; a1l = b1l; a1h = b1h;
        a2l = b2l; a2h = b2h; aal = bal; aah = bah;

        // prefetch row y+2 into slot b (clamp 510; clamped slot never consumed)
        const int yp = (y + 2 <= 510 ? y + 2 : 510);
        const int nrow = yp * WW;
        bS = pk2(D[nrow + WW + x_lo], D[nrow + WW + x_hi]);
        bE = pk2(D[nrow + x_lo + 1],  D[nrow + x_hi + 1]);
        bW = pk2(D[nrow + x_lo - 1],  D[nrow + x_hi - 1]);
        b0l = I0[nrow + x_lo]; b0h = I0[nrow + x_hi];
        b1l = I1[nrow + x_lo]; b1h = I1[nrow + x_hi];
        b2l = I2[nrow + x_lo]; b2h = I2[nrow + x_hi];
        bal = A2[nrow + x_lo]; bah = A2[nrow + x_hi];

        const float vf  = (y     - 256.0f) * INVF;
        const float vNf = (y - 1 - 256.0f) * INVF;
        const float vSf = (y + 1 - 256.0f) * INVF;
        const u64 v2  = bcast2(vf);
        const u64 vN2 = bcast2(vNf);
        const u64 vS2 = bcast2(vSf);

        const u64 dCE = sub2(dC2, dE2);
        const u64 dSC = sub2(dS2, dC2);
        const u64 dCW = sub2(dC2, dW2);
        const u64 dNC = sub2(dN2, dC2);

        const u64 vdc = mul2(v2, dC2);
        const u64 awx = fms2(u2, dC2, mul2(uE2, dE2));
        const u64 awy = mul2(v2, dCE);
        const u64 asx = mul2(u2, dSC);
        const u64 asy = fms2(vS2, dS2, vdc);
        const u64 aex = fms2(u2, dC2, mul2(uW2, dW2));
        const u64 aey = mul2(v2, dCW);
        const u64 anx = mul2(u2, dNC);
        const u64 any2 = fms2(vN2, dN2, vdc);

        const u64 nx = add2(fms2(awy, dSC, mul2(dCE, asy)),
                            fms2(aey, dNC, mul2(dCW, any2)));
        const u64 ny = add2(fms2(dCE, asx, mul2(awx, dSC)),
                            fms2(dCW, anx, mul2(aex, dNC)));
        const u64 nz = add2(fms2(awx, asy, mul2(awy, asx)),
                            fms2(aex, any2, mul2(aey, anx)));

        const u64 xx = mul2(nx, nx);
        const u64 yy = mul2(ny, ny);
        const u64 zz = mul2(nz, nz);
        const u64 mag2v = add2(xx, add2(yy, zz));

        float m2l, m2h;
        upk2(mag2v, m2l, m2h);
        const u64 r2inv = pk2(rsqrtf(m2l), rsqrtf(m2h));  // 1/mag

        const float m0l = fmaf(g0l, 0.5f, 0.5f);
        const float m0h = fmaf(g0h, 0.5f, 0.5f);
        const float kl = (m0l != 0.0f) ? 1.0f : 0.0f;
        const float kh = (v_hi && (m0h != 0.0f)) ? 1.0f : 0.0f;
        const u64 rho2 = pk2(all_ * kl, alh * kh);

        // Unscaled moment vector (SH constants deferred to solve):
        // Mv = rho * (mag, nz, nx, ny, q4/mag, xz/mag, yz/mag, (x2-y2)/mag, xy/mag)
        const u64 rr = mul2(rho2, r2inv);     // rho / mag
        u64 Mv[9];
        Mv[0] = mul2(rr, mag2v);              // rho * mag
        Mv[1] = mul2(rho2, nz);
        Mv[2] = mul2(rho2, nx);
        Mv[3] = mul2(rho2, ny);
        Mv[4] = mul2(rr, fms2(THREE2, zz, mag2v));   // (2z2-x2-y2) = 3z2 - mag2
        Mv[5] = mul2(rr, mul2(nx, nz));
        Mv[6] = mul2(rr, mul2(ny, nz));
        Mv[7] = mul2(rr, sub2(xx, yy));
        Mv[8] = mul2(rr, mul2(nx, ny));

        const u64 r0v = pk2(m0l, m0h);
        const u64 r1v = pk2(fmaf(g1l, 0.5f, 0.5f), fmaf(g1h, 0.5f, 0.5f));
        const u64 r2v = pk2(fmaf(g2l, 0.5f, 0.5f), fmaf(g2h, 0.5f, 0.5f));

        {
            int k = 0;
#pragma unroll
            for (int i = 0; i < 9; i++)
#pragma unroll
                for (int j = i; j < 9; j++) { s2[k] = fma2(Mv[i], Mv[j], s2[k]); k++; }
        }
#pragma unroll
        for (int i = 0; i < 9; i++) {
            s2[45 + i] = fma2(r0v, Mv[i], s2[45 + i]);
            s2[54 + i] = fma2(r1v, Mv[i], s2[54 + i]);
            s2[63 + i] = fma2(r2v, Mv[i], s2[63 + i]);
        }

        dN2 = dC2;
        dC2 = dS2;
    }

    // block reduction: pair-sum -> warp shuffle -> smem -> per-block partial
    __shared__ float red[4][NACC];
    const int lane = tid & 31;
    const int warp = tid >> 5;
#pragma unroll
    for (int k = 0; k < NACC; k++) {
        float lo, hi;
        upk2(s2[k], lo, hi);
        float v = lo + hi;
#pragma unroll
        for (int off = 16; off > 0; off >>= 1)
            v += __shfl_down_sync(0xffffffffu, v, off);
        if (lane == 0) red[warp][k] = v;
    }
    __syncthreads();
    const size_t pidx = ((size_t)b * NPART + (size_t)xb * NSTR + st) * NACC;
    for (int k = tid; k < NACC; k += 128) {
        g_part[pidx + k] = red[0][k] + red[1][k] + red[2][k] + red[3][k];
    }
}

#define NCOL 21   // GJ row: [0..8]=A, [9..11]=b, [12..20]=I -> A^{-1}

// grid = B blocks, 96 threads each. Block b solves batch b. All fp32.
// Applies the deferred SH-constant diagonal scaling: A = D M D, Atb = D t.
__global__ __launch_bounds__(96) void solve_k(float* __restrict__ out) {
    const int b = blockIdx.x;
    const int t = threadIdx.x;
    __shared__ float acc[NACC];

    const double PI_ = 3.14159;
    const float C0 = (float)(PI_ * sqrt(1.0 / (4.0 * PI_)));
    const float C1 = (float)(2.0 * PI_ / 3.0 * sqrt(3.0 / (4.0 * PI_)));
    const float C2 = (float)(PI_ / 4.0 * 0.5 * sqrt(5.0 / (4.0 * PI_)));
    const float C3 = (float)(PI_ / 4.0 * 3.0 * sqrt(5.0 / (12.0 * PI_)));
    const float C4 = (float)(PI_ / 4.0 * 3.0 * sqrt(5.0 / (48.0 * PI_)));
    const float CC[9] = {C0, C1, C1, C1, C2, C3, C3, C4, C3};

    // Phase 1: 72 threads, one element each; 8-chain chunked sum (MLP 8)
    if (t < NACC) {
        const float* p = g_part + (size_t)b * NPART * NACC + t;
        float f[NPART];
#pragma unroll
        for (int q = 0; q < NPART; q++) f[q] = p[q * NACC];
        float c[8];
#pragma unroll
        for (int i = 0; i < 8; i++) c[i] = 0.0f;
#pragma unroll
        for (int q = 0; q < NPART; q++) c[q & 7] += f[q];
        acc[t] = ((c[0] + c[1]) + (c[2] + c[3])) + ((c[4] + c[5]) + (c[6] + c[7]));
    }
    __syncthreads();

    if (t >= 32) return;
    const int lane = t;
    const unsigned FULL = 0xFFFFFFFFu;

    // per-lane copies of A row + b, with deferred constant scaling applied
    float Arow[9], bvec[3];
    const float Ci = (lane < 9) ? CC[lane] : 0.0f;
#pragma unroll
    for (int j = 0; j < 9; j++) {
        int i = lane < j ? lane : j;
        int jj = lane < j ? j : lane;
        Arow[j] = (lane < 9) ? acc[triidx(i, jj)] * (Ci * CC[j]) : 0.0f;
    }
#pragma unroll
    for (int c = 0; c < 3; c++)
        bvec[c] = (lane < 9) ? acc[45 + 9 * c + lane] * Ci : 0.0f;

    // fp32 Gauss-Jordan on [A | b | I] (SPD, no pivoting)
    float row[NCOL];
#pragma unroll
    for (int j = 0; j < 9; j++) row[j] = Arow[j];
#pragma unroll
    for (int c = 0; c < 3; c++) row[9 + c] = bvec[c];
#pragma unroll
    for (int j = 0; j < 9; j++) row[12 + j] = (lane == j) ? 1.0f : 0.0f;

#pragma unroll
    for (int col = 0; col < 9; col++) {
        const float pc = __shfl_sync(FULL, row[col], col);
        const float invp = __frcp_rn(pc);
        float piv[NCOL];
#pragma unroll
        for (int j = 0; j < NCOL; j++)
            piv[j] = __shfl_sync(FULL, row[j], col) * invp;
        if (lane == col) {
#pragma unroll
            for (int j = 0; j < NCOL; j++) row[j] = piv[j];
        } else {
            const float f = row[col];
#pragma unroll
            for (int j = 0; j < NCOL; j++) row[j] = fmaf(-f, piv[j], row[j]);
        }
    }
    // row[9..11] = x0, row[12..20] = A^{-1} row

    // refinement: r = b - A*x0 via compensated fp32 (TwoProd + TwoSum); dx = A^{-1}*r
#pragma unroll
    for (int c = 0; c < 3; c++) {
        float s = bvec[c], comp = 0.0f;
#pragma unroll
        for (int j = 0; j < 9; j++) {
            const float xj = __shfl_sync(FULL, row[9 + c], j);
            const float p = -Arow[j] * xj;
            const float perr = fmaf(-Arow[j], xj, -p);     // exact product error
            const float t1 = s + p;                         // TwoSum
            const float z = t1 - s;
            const float serr = (s - (t1 - z)) + (p - z);
            s = t1;
            comp += perr + serr;
        }
        const float rf = s + comp;
        float dx = 0.0f;
#pragma unroll
        for (int j = 0; j < 9; j++) {
            const float rj = __shfl_sync(FULL, rf, j);
            dx = fmaf(row[12 + j], rj, dx);
        }
        if (lane < 9)
            out[b * 27 + c * 9 + lane] = row[9 + c] + dx;
    }
}

extern "C" void kernel_launch(void* const* d_in, const int* in_sizes, int n_in,
                              void* d_out, int out_size) {
    const float* img = (const float*)d_in[0];   // input_img (B,3,H,W)
    const float* dep = (const float*)d_in[1];   // depth_target (B,1,H,W)
    const float* alb = (const float*)d_in[2];   // albedo (B,3,H,W)
    int B = in_sizes[1] / (HH * WW);
    if (B > BMAX) B = BMAX;

    dim3 grid(NXB, NSTR, B);
    accum_k<<<grid, 128>>>(img, dep, alb);
    solve_k<<<B, 96>>>((float*)d_out);
}

// round 14
// speedup vs baseline: 1.0904x; 1.0904x over previous
#include <cuda_runtime.h>
#include <math.h>

#define HH 512
#define WW 512
#define NACC 72          // 45 M upper-tri + 27 moment-Atb (unscaled by SH consts)
#define NXB 2
#define NSTR 18
#define NPART (NXB * NSTR)   // 36 blocks per batch image; grid = 288 = single wave
#define BMAX 8

__device__ float g_part[BMAX * NPART * NACC];

typedef unsigned long long u64;

__device__ __forceinline__ u64 pk2(float lo, float hi) {
    u64 r; asm("mov.b64 %0,{%1,%2};" : "=l"(r) : "f"(lo), "f"(hi)); return r;
}
__device__ __forceinline__ void upk2(u64 a, float& lo, float& hi) {
    asm("mov.b64 {%0,%1},%2;" : "=f"(lo), "=f"(hi) : "l"(a));
}
__device__ __forceinline__ u64 fma2(u64 a, u64 b, u64 c) {
    u64 d; asm("fma.rn.f32x2 %0,%1,%2,%3;" : "=l"(d) : "l"(a), "l"(b), "l"(c)); return d;
}
__device__ __forceinline__ u64 mul2(u64 a, u64 b) {
    u64 d; asm("mul.rn.f32x2 %0,%1,%2;" : "=l"(d) : "l"(a), "l"(b)); return d;
}
__device__ __forceinline__ u64 add2(u64 a, u64 b) {
    u64 d; asm("add.rn.f32x2 %0,%1,%2;" : "=l"(d) : "l"(a), "l"(b)); return d;
}
__device__ __forceinline__ u64 neg2(u64 a) { return a ^ 0x8000000080000000ULL; }
__device__ __forceinline__ u64 sub2(u64 a, u64 b) { return fma2(b, 0xBF800000BF800000ULL, a); }
__device__ __forceinline__ u64 fms2(u64 a, u64 b, u64 c) { return fma2(a, b, neg2(c)); }
__device__ __forceinline__ u64 bcast2(float v) { return pk2(v, v); }

__device__ __forceinline__ int triidx(int i, int j) {   // upper-tri, i<=j
    return 9 * i - (i * (i - 1)) / 2 + (j - i);
}

__global__ __launch_bounds__(128) void accum_k(const float* __restrict__ img,
                                               const float* __restrict__ dep,
                                               const float* __restrict__ alb) {
    const int tid = threadIdx.x;
    const int xb = blockIdx.x;   // 0..1
    const int st = blockIdx.y;   // 0..17
    const int b  = blockIdx.z;

    const int x_lo = 1 + xb * 256 + tid;    // <= 384, always valid
    int x_hi = x_lo + 128;
    const bool v_hi = (x_hi <= 510);
    if (!v_hi) x_hi = 510;                  // clamp; contribution zeroed below

    const int y0 = 1 + (510 * st) / NSTR;
    const int y1 = 1 + (510 * (st + 1)) / NSTR;

    const float* __restrict__ D  = dep + (size_t)b * HH * WW;
    const float* __restrict__ I0 = img + (size_t)b * 3 * HH * WW;
    const float* __restrict__ I1 = I0 + HH * WW;
    const float* __restrict__ I2 = I1 + HH * WW;
    const float* __restrict__ A2 = alb + (size_t)b * 3 * HH * WW + 2 * HH * WW;

    const float INVF = (float)(1.0 / 608.365);
    const u64 HALF2  = 0x3F0000003F000000ULL;
    const u64 THREE2 = 0x4040000040400000ULL;

    const u64 u2  = pk2((x_lo     - 256.0f) * INVF, (x_hi     - 256.0f) * INVF);
    const u64 uE2 = pk2((x_lo + 1 - 256.0f) * INVF, (x_hi + 1 - 256.0f) * INVF);
    const u64 uW2 = pk2((x_lo - 1 - 256.0f) * INVF, (x_hi - 1 - 256.0f) * INVF);

    u64 s2[NACC];
#pragma unroll
    for (int k = 0; k < NACC; k++) s2[k] = 0ULL;

    // rolling center-column depth (transformed)
    u64 dN2 = fma2(pk2(D[(y0 - 1) * WW + x_lo], D[(y0 - 1) * WW + x_hi]), HALF2, HALF2);
    u64 dC2 = fma2(pk2(D[y0 * WW + x_lo],       D[y0 * WW + x_hi]),       HALF2, HALF2);

    // 2-deep software pipeline: slot a = row y, slot b = row y+1.
    // Max consumed row is 510 (south neighbor 511 valid); prefetch clamps to
    // 510 -> reads at most row 511 (in-bounds); the clamped duplicate slot is
    // only created PAST the last consumed row and is never read.
    int ra = y0 * WW;
    u64 aS = pk2(D[ra + WW + x_lo], D[ra + WW + x_hi]);
    u64 aE = pk2(D[ra + x_lo + 1],  D[ra + x_hi + 1]);
    u64 aW = pk2(D[ra + x_lo - 1],  D[ra + x_hi - 1]);
    float a0l = I0[ra + x_lo], a0h = I0[ra + x_hi];
    float a1l = I1[ra + x_lo], a1h = I1[ra + x_hi];
    float a2l = I2[ra + x_lo], a2h = I2[ra + x_hi];
    float aal = A2[ra + x_lo], aah = A2[ra + x_hi];

    int rb = (y0 + 1 <= 510 ? y0 + 1 : 510) * WW;
    u64 bS = pk2(D[rb + WW + x_lo], D[rb + WW + x_hi]);
    u64 bE = pk2(D[rb + x_lo + 1],  D[rb + x_hi + 1]);
    u64 bW = pk2(D[rb + x_lo - 1],  D[rb + x_hi - 1]);
    float b0l = I0[rb + x_lo], b0h = I0[rb + x_hi];
    float b1l = I1[rb + x_lo], b1h = I1[rb + x_hi];
    float b2l = I2[rb + x_lo], b2h = I2[rb + x_hi];
    float bal = A2[rb + x_lo], bah = A2[rb + x_hi];

#pragma unroll 2
    for (int y = y0; y < y1; y++) {
        // consume slot a (row y)
        const u64 dS2 = fma2(aS, HALF2, HALF2);
        const u64 dE2 = fma2(aE, HALF2, HALF2);
        const u64 dW2 = fma2(aW, HALF2, HALF2);
        const float g0l = a0l, g0h = a0h;
        const float g1l = a1l, g1h = a1h;
        const float g2l = a2l, g2h = a2h;
        const float all_ = aal, alh = aah;

        // shift b -> a  (renamed away by the unroll-2)
        aS = bS; aE = bE; aW = bW;
        a0l = b0l; a0h = b0h; a1l = b1l; a1h = b1h;
        a2l = b2l; a2h = b2h; aal = bal; aah = bah;

        // prefetch row y+2 into slot b (clamp 510; clamped slot never consumed)
        const int yp = (y + 2 <= 510 ? y + 2 : 510);
        const int nrow = yp * WW;
        bS = pk2(D[nrow + WW + x_lo], D[nrow + WW + x_hi]);
        bE = pk2(D[nrow + x_lo + 1],  D[nrow + x_hi + 1]);
        bW = pk2(D[nrow + x_lo - 1],  D[nrow + x_hi - 1]);
        b0l = I0[nrow + x_lo]; b0h = I0[nrow + x_hi];
        b1l = I1[nrow + x_lo]; b1h = I1[nrow + x_hi];
        b2l = I2[nrow + x_lo]; b2h = I2[nrow + x_hi];
        bal = A2[nrow + x_lo]; bah = A2[nrow + x_hi];

        const float vf  = (y     - 256.0f) * INVF;
        const float vNf = (y - 1 - 256.0f) * INVF;
        const float vSf = (y + 1 - 256.0f) * INVF;
        const u64 v2  = bcast2(vf);
        const u64 vN2 = bcast2(vNf);
        const u64 vS2 = bcast2(vSf);

        const u64 dCE = sub2(dC2, dE2);
        const u64 dSC = sub2(dS2, dC2);
        const u64 dCW = sub2(dC2, dW2);
        const u64 dNC = sub2(dN2, dC2);

        const u64 vdc = mul2(v2, dC2);
        const u64 awx = fms2(u2, dC2, mul2(uE2, dE2));
        const u64 awy = mul2(v2, dCE);
        const u64 asx = mul2(u2, dSC);
        const u64 asy = fms2(vS2, dS2, vdc);
        const u64 aex = fms2(u2, dC2, mul2(uW2, dW2));
        const u64 aey = mul2(v2, dCW);
        const u64 anx = mul2(u2, dNC);
        const u64 any2 = fms2(vN2, dN2, vdc);

        const u64 nx = add2(fms2(awy, dSC, mul2(dCE, asy)),
                            fms2(aey, dNC, mul2(dCW, any2)));
        const u64 ny = add2(fms2(dCE, asx, mul2(awx, dSC)),
                            fms2(dCW, anx, mul2(aex, dNC)));
        const u64 nz = add2(fms2(awx, asy, mul2(awy, asx)),
                            fms2(aex, any2, mul2(aey, anx)));

        const u64 xx = mul2(nx, nx);
        const u64 yy = mul2(ny, ny);
        const u64 zz = mul2(nz, nz);
        const u64 mag2v = add2(xx, add2(yy, zz));

        float m2l, m2h;
        upk2(mag2v, m2l, m2h);
        const u64 r2inv = pk2(rsqrtf(m2l), rsqrtf(m2h));  // 1/mag

        const float m0l = fmaf(g0l, 0.5f, 0.5f);
        const float m0h = fmaf(g0h, 0.5f, 0.5f);
        const float kl = (m0l != 0.0f) ? 1.0f : 0.0f;
        const float kh = (v_hi && (m0h != 0.0f)) ? 1.0f : 0.0f;
        const u64 rho2 = pk2(all_ * kl, alh * kh);

        // Unscaled moment vector (SH constants deferred to solve):
        const u64 rr = mul2(rho2, r2inv);     // rho / mag
        u64 Mv[9];
        Mv[0] = mul2(rr, mag2v);              // rho * mag
        Mv[1] = mul2(rho2, nz);
        Mv[2] = mul2(rho2, nx);
        Mv[3] = mul2(rho2, ny);
        Mv[4] = mul2(rr, fms2(THREE2, zz, mag2v));   // (2z2-x2-y2) = 3z2 - mag2
        Mv[5] = mul2(rr, mul2(nx, nz));
        Mv[6] = mul2(rr, mul2(ny, nz));
        Mv[7] = mul2(rr, sub2(xx, yy));
        Mv[8] = mul2(rr, mul2(nx, ny));

        const u64 r0v = pk2(m0l, m0h);
        const u64 r1v = pk2(fmaf(g1l, 0.5f, 0.5f), fmaf(g1h, 0.5f, 0.5f));
        const u64 r2v = pk2(fmaf(g2l, 0.5f, 0.5f), fmaf(g2h, 0.5f, 0.5f));

        {
            int k = 0;
#pragma unroll
            for (int i = 0; i < 9; i++)
#pragma unroll
                for (int j = i; j < 9; j++) { s2[k] = fma2(Mv[i], Mv[j], s2[k]); k++; }
        }
#pragma unroll
        for (int i = 0; i < 9; i++) {
            s2[45 + i] = fma2(r0v, Mv[i], s2[45 + i]);
            s2[54 + i] = fma2(r1v, Mv[i], s2[54 + i]);
            s2[63 + i] = fma2(r2v, Mv[i], s2[63 + i]);
        }

        dN2 = dC2;
        dC2 = dS2;
    }

    // block reduction: pair-sum -> warp shuffle -> smem -> per-block partial
    __shared__ float red[4][NACC];
    const int lane = tid & 31;
    const int warp = tid >> 5;
#pragma unroll
    for (int k = 0; k < NACC; k++) {
        float lo, hi;
        upk2(s2[k], lo, hi);
        float v = lo + hi;
#pragma unroll
        for (int off = 16; off > 0; off >>= 1)
            v += __shfl_down_sync(0xffffffffu, v, off);
        if (lane == 0) red[warp][k] = v;
    }
    __syncthreads();
    const size_t pidx = ((size_t)b * NPART + (size_t)xb * NSTR + st) * NACC;
    for (int k = tid; k < NACC; k += 128) {
        g_part[pidx + k] = red[0][k] + red[1][k] + red[2][k] + red[3][k];
    }
}

#define NCOL 21   // GJ row: [0..8]=A, [9..11]=b, [12..20]=I -> A^{-1}

// grid = B blocks, 96 threads each. Block b solves batch b. All fp32.
// Applies the deferred SH-constant diagonal scaling: A = D M D, Atb = D t.
__global__ __launch_bounds__(96) void solve_k(float* __restrict__ out) {
    const int b = blockIdx.x;
    const int t = threadIdx.x;
    __shared__ float acc[NACC];

    const double PI_ = 3.14159;
    const float C0 = (float)(PI_ * sqrt(1.0 / (4.0 * PI_)));
    const float C1 = (float)(2.0 * PI_ / 3.0 * sqrt(3.0 / (4.0 * PI_)));
    const float C2 = (float)(PI_ / 4.0 * 0.5 * sqrt(5.0 / (4.0 * PI_)));
    const float C3 = (float)(PI_ / 4.0 * 3.0 * sqrt(5.0 / (12.0 * PI_)));
    const float C4 = (float)(PI_ / 4.0 * 3.0 * sqrt(5.0 / (48.0 * PI_)));
    const float CC[9] = {C0, C1, C1, C1, C2, C3, C3, C4, C3};

    // Phase 1: 72 threads, one element each; fully-unrolled chunked sum (MLP)
    if (t < NACC) {
        const float* p = g_part + (size_t)b * NPART * NACC + t;
        float f[NPART];
#pragma unroll
        for (int q = 0; q < NPART; q++) f[q] = p[q * NACC];
        float c[4];
#pragma unroll
        for (int i = 0; i < 4; i++) c[i] = 0.0f;
#pragma unroll
        for (int q = 0; q < NPART; q++) c[q & 3] += f[q];
        acc[t] = (c[0] + c[1]) + (c[2] + c[3]);
    }
    __syncthreads();

    if (t >= 32) return;
    const int lane = t;
    const unsigned FULL = 0xFFFFFFFFu;

    // per-lane copies of A row + b, with deferred constant scaling applied
    float Arow[9], bvec[3];
    const float Ci = (lane < 9) ? CC[lane] : 0.0f;
#pragma unroll
    for (int j = 0; j < 9; j++) {
        int i = lane < j ? lane : j;
        int jj = lane < j ? j : lane;
        Arow[j] = (lane < 9) ? acc[triidx(i, jj)] * (Ci * CC[j]) : 0.0f;
    }
#pragma unroll
    for (int c = 0; c < 3; c++)
        bvec[c] = (lane < 9) ? acc[45 + 9 * c + lane] * Ci : 0.0f;

    // fp32 Gauss-Jordan on [A | b | I] (SPD, no pivoting)
    float row[NCOL];
#pragma unroll
    for (int j = 0; j < 9; j++) row[j] = Arow[j];
#pragma unroll
    for (int c = 0; c < 3; c++) row[9 + c] = bvec[c];
#pragma unroll
    for (int j = 0; j < 9; j++) row[12 + j] = (lane == j) ? 1.0f : 0.0f;

#pragma unroll
    for (int col = 0; col < 9; col++) {
        const float pc = __shfl_sync(FULL, row[col], col);
        const float invp = __frcp_rn(pc);
        float piv[NCOL];
#pragma unroll
        for (int j = 0; j < NCOL; j++)
            piv[j] = __shfl_sync(FULL, row[j], col) * invp;
        if (lane == col) {
#pragma unroll
            for (int j = 0; j < NCOL; j++) row[j] = piv[j];
        } else {
            const float f = row[col];
#pragma unroll
            for (int j = 0; j < NCOL; j++) row[j] = fmaf(-f, piv[j], row[j]);
        }
    }
    // row[9..11] = x0, row[12..20] = A^{-1} row

    // refinement: r = b - A*x0 via compensated fp32 (TwoProd + TwoSum); dx = A^{-1}*r
#pragma unroll
    for (int c = 0; c < 3; c++) {
        float s = bvec[c], comp = 0.0f;
#pragma unroll
        for (int j = 0; j < 9; j++) {
            const float xj = __shfl_sync(FULL, row[9 + c], j);
            const float p = -Arow[j] * xj;
            const float perr = fmaf(-Arow[j], xj, -p);     // exact product error
            const float t1 = s + p;                         // TwoSum
            const float z = t1 - s;
            const float serr = (s - (t1 - z)) + (p - z);
            s = t1;
            comp += perr + serr;
        }
        const float rf = s + comp;
        float dx = 0.0f;
#pragma unroll
        for (int j = 0; j < 9; j++) {
            const float rj = __shfl_sync(FULL, rf, j);
            dx = fmaf(row[12 + j], rj, dx);
        }
        if (lane < 9)
            out[b * 27 + c * 9 + lane] = row[9 + c] + dx;
    }
}

extern "C" void kernel_launch(void* const* d_in, const int* in_sizes, int n_in,
                              void* d_out, int out_size) {
    const float* img = (const float*)d_in[0];   // input_img (B,3,H,W)
    const float* dep = (const float*)d_in[1];   // depth_target (B,1,H,W)
    const float* alb = (const float*)d_in[2];   // albedo (B,3,H,W)
    int B = in_sizes[1] / (HH * WW);
    if (B > BMAX) B = BMAX;

    dim3 grid(NXB, NSTR, B);
    accum_k<<<grid, 128>>>(img, dep, alb);
    solve_k<<<B, 96>>>((float*)d_out);
}

// round 15
// speedup vs baseline: 1.1615x; 1.0652x over previous
#include <cuda_runtime.h>
#include <math.h>

#define HH 512
#define WW 512
#define NACC 72          // 45 M upper-tri + 27 moment-Atb (unscaled by SH consts)
#define NXB 2
#define NSTR 18
#define NPART (NXB * NSTR)   // 36 blocks per batch image; grid = 288 = single wave
#define BMAX 8

__device__ float g_part[BMAX * NPART * NACC];

typedef unsigned long long u64;

__device__ __forceinline__ u64 pk2(float lo, float hi) {
    u64 r; asm("mov.b64 %0,{%1,%2};" : "=l"(r) : "f"(lo), "f"(hi)); return r;
}
__device__ __forceinline__ void upk2(u64 a, float& lo, float& hi) {
    asm("mov.b64 {%0,%1},%2;" : "=f"(lo), "=f"(hi) : "l"(a));
}
__device__ __forceinline__ u64 fma2(u64 a, u64 b, u64 c) {
    u64 d; asm("fma.rn.f32x2 %0,%1,%2,%3;" : "=l"(d) : "l"(a), "l"(b), "l"(c)); return d;
}
__device__ __forceinline__ u64 mul2(u64 a, u64 b) {
    u64 d; asm("mul.rn.f32x2 %0,%1,%2;" : "=l"(d) : "l"(a), "l"(b)); return d;
}
__device__ __forceinline__ u64 add2(u64 a, u64 b) {
    u64 d; asm("add.rn.f32x2 %0,%1,%2;" : "=l"(d) : "l"(a), "l"(b)); return d;
}
__device__ __forceinline__ u64 neg2(u64 a) { return a ^ 0x8000000080000000ULL; }
__device__ __forceinline__ u64 sub2(u64 a, u64 b) { return fma2(b, 0xBF800000BF800000ULL, a); }
__device__ __forceinline__ u64 fms2(u64 a, u64 b, u64 c) { return fma2(a, b, neg2(c)); }
__device__ __forceinline__ u64 bcast2(float v) { return pk2(v, v); }

__device__ __forceinline__ int triidx(int i, int j) {   // upper-tri, i<=j
    return 9 * i - (i * (i - 1)) / 2 + (j - i);
}

__global__ __launch_bounds__(128) void accum_k(const float* __restrict__ img,
                                               const float* __restrict__ dep,
                                               const float* __restrict__ alb) {
    const int tid = threadIdx.x;
    const int xb = blockIdx.x;   // 0..1
    const int st = blockIdx.y;   // 0..17
    const int b  = blockIdx.z;

    const int x_lo = 1 + xb * 256 + tid;    // <= 384, always valid
    int x_hi = x_lo + 128;
    const bool v_hi = (x_hi <= 510);
    if (!v_hi) x_hi = 510;                  // clamp; contribution zeroed below

    const int y0 = 1 + (510 * st) / NSTR;
    const int y1 = 1 + (510 * (st + 1)) / NSTR;

    const float* __restrict__ D  = dep + (size_t)b * HH * WW;
    const float* __restrict__ I0 = img + (size_t)b * 3 * HH * WW;
    const float* __restrict__ I1 = I0 + HH * WW;
    const float* __restrict__ I2 = I1 + HH * WW;
    const float* __restrict__ A2 = alb + (size_t)b * 3 * HH * WW + 2 * HH * WW;

    const float INVF = (float)(1.0 / 608.365);
    const u64 HALF2  = 0x3F0000003F000000ULL;
    const u64 THREE2 = 0x4040000040400000ULL;

    const u64 u2  = pk2((x_lo     - 256.0f) * INVF, (x_hi     - 256.0f) * INVF);
    const u64 uE2 = pk2((x_lo + 1 - 256.0f) * INVF, (x_hi + 1 - 256.0f) * INVF);
    const u64 uW2 = pk2((x_lo - 1 - 256.0f) * INVF, (x_hi - 1 - 256.0f) * INVF);

    u64 s2[NACC];
#pragma unroll
    for (int k = 0; k < NACC; k++) s2[k] = 0ULL;

    // rolling center-column depth (transformed)
    u64 dN2 = fma2(pk2(D[(y0 - 1) * WW + x_lo], D[(y0 - 1) * WW + x_hi]), HALF2, HALF2);
    u64 dC2 = fma2(pk2(D[y0 * WW + x_lo],       D[y0 * WW + x_hi]),       HALF2, HALF2);

    // rolling row coordinates (replaces per-iter I2F + FMUL)
    float vNf = (y0 - 1 - 256.0f) * INVF;
    float vf  = (y0     - 256.0f) * INVF;
    float vSf = (y0 + 1 - 256.0f) * INVF;

    // 2-deep software pipeline: slot a = row y, slot b = row y+1.
    // Max consumed row is 510 (south neighbor 511 valid); prefetch clamps to
    // 510 -> reads at most row 511 (in-bounds); the clamped duplicate slot is
    // only created PAST the last consumed row and is never read.
    int ra = y0 * WW;
    u64 aS = pk2(D[ra + WW + x_lo], D[ra + WW + x_hi]);
    u64 aE = pk2(D[ra + x_lo + 1],  D[ra + x_hi + 1]);
    u64 aW = pk2(D[ra + x_lo - 1],  D[ra + x_hi - 1]);
    float a0l = I0[ra + x_lo], a0h = I0[ra + x_hi];
    float a1l = I1[ra + x_lo], a1h = I1[ra + x_hi];
    float a2l = I2[ra + x_lo], a2h = I2[ra + x_hi];
    float aal = A2[ra + x_lo], aah = A2[ra + x_hi];

    int rb = (y0 + 1 <= 510 ? y0 + 1 : 510) * WW;
    u64 bS = pk2(D[rb + WW + x_lo], D[rb + WW + x_hi]);
    u64 bE = pk2(D[rb + x_lo + 1],  D[rb + x_hi + 1]);
    u64 bW = pk2(D[rb + x_lo - 1],  D[rb + x_hi - 1]);
    float b0l = I0[rb + x_lo], b0h = I0[rb + x_hi];
    float b1l = I1[rb + x_lo], b1h = I1[rb + x_hi];
    float b2l = I2[rb + x_lo], b2h = I2[rb + x_hi];
    float bal = A2[rb + x_lo], bah = A2[rb + x_hi];

#pragma unroll 4
    for (int y = y0; y < y1; y++) {
        // consume slot a (row y)
        const u64 dS2 = fma2(aS, HALF2, HALF2);
        const u64 dE2 = fma2(aE, HALF2, HALF2);
        const u64 dW2 = fma2(aW, HALF2, HALF2);
        const float g0l = a0l, g0h = a0h;
        const float g1l = a1l, g1h = a1h;
        const float g2l = a2l, g2h = a2h;
        const float all_ = aal, alh = aah;

        // shift b -> a  (renamed away by the unroll)
        aS = bS; aE = bE; aW = bW;
        a0l = b0l; a0h = b0h; a1l = b1l; a1h = b1h;
        a2l = b2l; a2h = b2h; aal = bal; aah = bah;

        // prefetch row y+2 into slot b (clamp 510; clamped slot never consumed)
        const int yp = (y + 2 <= 510 ? y + 2 : 510);
        const int nrow = yp * WW;
        bS = pk2(D[nrow + WW + x_lo], D[nrow + WW + x_hi]);
        bE = pk2(D[nrow + x_lo + 1],  D[nrow + x_hi + 1]);
        bW = pk2(D[nrow + x_lo - 1],  D[nrow + x_hi - 1]);
        b0l = I0[nrow + x_lo]; b0h = I0[nrow + x_hi];
        b1l = I1[nrow + x_lo]; b1h = I1[nrow + x_hi];
        b2l = I2[nrow + x_lo]; b2h = I2[nrow + x_hi];
        bal = A2[nrow + x_lo]; bah = A2[nrow + x_hi];

        const u64 v2  = bcast2(vf);
        const u64 vN2 = bcast2(vNf);
        const u64 vS2 = bcast2(vSf);

        const u64 dCE = sub2(dC2, dE2);
        const u64 dSC = sub2(dS2, dC2);
        const u64 dCW = sub2(dC2, dW2);
        const u64 dNC = sub2(dN2, dC2);

        const u64 vdc = mul2(v2, dC2);
        const u64 awx = fms2(u2, dC2, mul2(uE2, dE2));
        const u64 awy = mul2(v2, dCE);
        const u64 asx = mul2(u2, dSC);
        const u64 asy = fms2(vS2, dS2, vdc);
        const u64 aex = fms2(u2, dC2, mul2(uW2, dW2));
        const u64 aey = mul2(v2, dCW);
        const u64 anx = mul2(u2, dNC);
        const u64 any2 = fms2(vN2, dN2, vdc);

        const u64 nx = add2(fms2(awy, dSC, mul2(dCE, asy)),
                            fms2(aey, dNC, mul2(dCW, any2)));
        const u64 ny = add2(fms2(dCE, asx, mul2(awx, dSC)),
                            fms2(dCW, anx, mul2(aex, dNC)));
        const u64 nz = add2(fms2(awx, asy, mul2(awy, asx)),
                            fms2(aex, any2, mul2(aey, anx)));

        const u64 xx = mul2(nx, nx);
        const u64 yy = mul2(ny, ny);
        const u64 zz = mul2(nz, nz);
        const u64 mag2v = add2(xx, add2(yy, zz));

        float m2l, m2h;
        upk2(mag2v, m2l, m2h);
        const u64 r2inv = pk2(rsqrtf(m2l), rsqrtf(m2h));  // 1/mag

        const float m0l = fmaf(g0l, 0.5f, 0.5f);
        const float m0h = fmaf(g0h, 0.5f, 0.5f);
        const float kl = (m0l != 0.0f) ? 1.0f : 0.0f;
        const float kh = (v_hi && (m0h != 0.0f)) ? 1.0f : 0.0f;
        const u64 rho2 = pk2(all_ * kl, alh * kh);

        // Unscaled moment vector (SH constants deferred to solve):
        const u64 rr = mul2(rho2, r2inv);     // rho / mag
        u64 Mv[9];
        Mv[0] = mul2(rr, mag2v);              // rho * mag
        Mv[1] = mul2(rho2, nz);
        Mv[2] = mul2(rho2, nx);
        Mv[3] = mul2(rho2, ny);
        Mv[4] = mul2(rr, fms2(THREE2, zz, mag2v));   // (2z2-x2-y2) = 3z2 - mag2
        Mv[5] = mul2(rr, mul2(nx, nz));
        Mv[6] = mul2(rr, mul2(ny, nz));
        Mv[7] = mul2(rr, sub2(xx, yy));
        Mv[8] = mul2(rr, mul2(nx, ny));

        const u64 r0v = pk2(m0l, m0h);
        const u64 r1v = pk2(fmaf(g1l, 0.5f, 0.5f), fmaf(g1h, 0.5f, 0.5f));
        const u64 r2v = pk2(fmaf(g2l, 0.5f, 0.5f), fmaf(g2h, 0.5f, 0.5f));

        {
            int k = 0;
#pragma unroll
            for (int i = 0; i < 9; i++)
#pragma unroll
                for (int j = i; j < 9; j++) { s2[k] = fma2(Mv[i], Mv[j], s2[k]); k++; }
        }
#pragma unroll
        for (int i = 0; i < 9; i++) {
            s2[45 + i] = fma2(r0v, Mv[i], s2[45 + i]);
            s2[54 + i] = fma2(r1v, Mv[i], s2[54 + i]);
            s2[63 + i] = fma2(r2v, Mv[i], s2[63 + i]);
        }

        dN2 = dC2;
        dC2 = dS2;
        vNf = vf; vf = vSf; vSf += INVF;
    }

    // block reduction: pair-sum -> warp shuffle -> smem -> per-block partial
    __shared__ float red[4][NACC];
    const int lane = tid & 31;
    const int warp = tid >> 5;
#pragma unroll
    for (int k = 0; k < NACC; k++) {
        float lo, hi;
        upk2(s2[k], lo, hi);
        float v = lo + hi;
#pragma unroll
        for (int off = 16; off > 0; off >>= 1)
            v += __shfl_down_sync(0xffffffffu, v, off);
        if (lane == 0) red[warp][k] = v;
    }
    __syncthreads();
    const size_t pidx = ((size_t)b * NPART + (size_t)xb * NSTR + st) * NACC;
    for (int k = tid; k < NACC; k += 128) {
        g_part[pidx + k] = red[0][k] + red[1][k] + red[2][k] + red[3][k];
    }
}

#define NCOL 21   // GJ row: [0..8]=A, [9..11]=b, [12..20]=I -> A^{-1}

// grid = B blocks, 96 threads each. Block b solves batch b. All fp32.
// Applies the deferred SH-constant diagonal scaling: A = D M D, Atb = D t.
__global__ __launch_bounds__(96) void solve_k(float* __restrict__ out) {
    const int b = blockIdx.x;
    const int t = threadIdx.x;
    __shared__ float acc[NACC];

    const double PI_ = 3.14159;
    const float C0 = (float)(PI_ * sqrt(1.0 / (4.0 * PI_)));
    const float C1 = (float)(2.0 * PI_ / 3.0 * sqrt(3.0 / (4.0 * PI_)));
    const float C2 = (float)(PI_ / 4.0 * 0.5 * sqrt(5.0 / (4.0 * PI_)));
    const float C3 = (float)(PI_ / 4.0 * 3.0 * sqrt(5.0 / (12.0 * PI_)));
    const float C4 = (float)(PI_ / 4.0 * 3.0 * sqrt(5.0 / (48.0 * PI_)));
    const float CC[9] = {C0, C1, C1, C1, C2, C3, C3, C4, C3};

    // Phase 1: 72 threads, one element each; fully-unrolled chunked sum (MLP)
    if (t < NACC) {
        const float* p = g_part + (size_t)b * NPART * NACC + t;
        float f[NPART];
#pragma unroll
        for (int q = 0; q < NPART; q++) f[q] = p[q * NACC];
        float c[4];
#pragma unroll
        for (int i = 0; i < 4; i++) c[i] = 0.0f;
#pragma unroll
        for (int q = 0; q < NPART; q++) c[q & 3] += f[q];
        acc[t] = (c[0] + c[1]) + (c[2] + c[3]);
    }
    __syncthreads();

    if (t >= 32) return;
    const int lane = t;
    const unsigned FULL = 0xFFFFFFFFu;

    // per-lane copies of A row + b, with deferred constant scaling applied
    float Arow[9], bvec[3];
    const float Ci = (lane < 9) ? CC[lane] : 0.0f;
#pragma unroll
    for (int j = 0; j < 9; j++) {
        int i = lane < j ? lane : j;
        int jj = lane < j ? j : lane;
        Arow[j] = (lane < 9) ? acc[triidx(i, jj)] * (Ci * CC[j]) : 0.0f;
    }
#pragma unroll
    for (int c = 0; c < 3; c++)
        bvec[c] = (lane < 9) ? acc[45 + 9 * c + lane] * Ci : 0.0f;

    // fp32 Gauss-Jordan on [A | b | I] (SPD, no pivoting)
    float row[NCOL];
#pragma unroll
    for (int j = 0; j < 9; j++) row[j] = Arow[j];
#pragma unroll
    for (int c = 0; c < 3; c++) row[9 + c] = bvec[c];
#pragma unroll
    for (int j = 0; j < 9; j++) row[12 + j] = (lane == j) ? 1.0f : 0.0f;

#pragma unroll
    for (int col = 0; col < 9; col++) {
        const float pc = __shfl_sync(FULL, row[col], col);
        const float invp = __frcp_rn(pc);
        float piv[NCOL];
#pragma unroll
        for (int j = 0; j < NCOL; j++)
            piv[j] = __shfl_sync(FULL, row[j], col) * invp;
        if (lane == col) {
#pragma unroll
            for (int j = 0; j < NCOL; j++) row[j] = piv[j];
        } else {
            const float f = row[col];
#pragma unroll
            for (int j = 0; j < NCOL; j++) row[j] = fmaf(-f, piv[j], row[j]);
        }
    }
    // row[9..11] = x0, row[12..20] = A^{-1} row

    // refinement: r = b - A*x0 via compensated fp32 (TwoProd + TwoSum); dx = A^{-1}*r
#pragma unroll
    for (int c = 0; c < 3; c++) {
        float s = bvec[c], comp = 0.0f;
#pragma unroll
        for (int j = 0; j < 9; j++) {
            const float xj = __shfl_sync(FULL, row[9 + c], j);
            const float p = -Arow[j] * xj;
            const float perr = fmaf(-Arow[j], xj, -p);     // exact product error
            const float t1 = s + p;                         // TwoSum
            const float z = t1 - s;
            const float serr = (s - (t1 - z)) + (p - z);
            s = t1;
            comp += perr + serr;
        }
        const float rf = s + comp;
        float dx = 0.0f;
#pragma unroll
        for (int j = 0; j < 9; j++) {
            const float rj = __shfl_sync(FULL, rf, j);
            dx = fmaf(row[12 + j], rj, dx);
        }
        if (lane < 9)
            out[b * 27 + c * 9 + lane] = row[9 + c] + dx;
    }
}

extern "C" void kernel_launch(void* const* d_in, const int* in_sizes, int n_in,
                              void* d_out, int out_size) {
    const float* img = (const float*)d_in[0];   // input_img (B,3,H,W)
    const float* dep = (const float*)d_in[1];   // depth_target (B,1,H,W)
    const float* alb = (const float*)d_in[2];   // albedo (B,3,H,W)
    int B = in_sizes[1] / (HH * WW);
    if (B > BMAX) B = BMAX;

    dim3 grid(NXB, NSTR, B);
    accum_k<<<grid, 128>>>(img, dep, alb);
    solve_k<<<B, 96>>>((float*)d_out);
}